// round 2
// baseline (speedup 1.0000x reference)
#include <cuda_runtime.h>
#include <cstdint>

// Problem constants
constexpr int B_  = 256;
constexpr int T_  = 512;
constexpr int D_  = 128;
constexpr int H_  = 256;
constexpr int MTOT = B_ * T_;              // 131072 rows for projection GEMM
constexpr size_t MH = (size_t)MTOT * H_;   // elements per gate in g_xp

// Scan decomposition
constexpr int NC  = 8;    // column groups (each owns 32 columns of U)
constexpr int HC  = 32;   // columns per group
constexpr int NBG = 16;   // batch groups
constexpr int NB  = 16;   // batch rows per group
// 128 CTAs total, 256 threads each (8 warps x 32 lanes)

// ---------------- device scratch (no runtime allocation allowed) ----------------
__device__ float g_xp[3 * MH];               // projected inputs: [gate][m][H]  (~403MB)
__device__ float g_h [NBG][NB][H_];          // h_t exchange
__device__ float g_rh[NBG][NB][H_];          // (r * h_dec) exchange
__device__ unsigned int g_ctr[NBG][2];       // per-group barrier counters

// ---------------- f32x2 helpers (packed FFMA2 — 2 FMAs/instr) ----------------
__device__ __forceinline__ unsigned long long pack2(float a, float b) {
    unsigned long long r;
    asm("mov.b64 %0, {%1,%2};" : "=l"(r) : "f"(a), "f"(b));
    return r;
}
__device__ __forceinline__ void fma2(unsigned long long& d, unsigned long long a, unsigned long long b) {
    asm("fma.rn.f32x2 %0, %1, %2, %0;" : "+l"(d) : "l"(a), "l"(b));
}
__device__ __forceinline__ float fold2(unsigned long long v) {
    float lo, hi;
    asm("mov.b64 {%0,%1}, %2;" : "=f"(lo), "=f"(hi) : "l"(v));
    return lo + hi;
}

__device__ __forceinline__ float sigmoid_(float v) {
    float e = __expf(-v);
    return __fdividef(1.f, 1.f + e);
}
__device__ __forceinline__ float tanh_(float v) {
    float e = __expf(2.f * v);
    return __fdividef(e - 1.f, e + 1.f);
}

// ================= projection GEMM: g_xp[g] = x @ W_g + b_g =================
// x:[131072,128] row-major, W:[128,256] row-major. Tile 128M x 64N, BK=32.
__global__ __launch_bounds__(256) void proj_kernel(
    const float* __restrict__ x,
    const float* __restrict__ Wz, const float* __restrict__ Wr, const float* __restrict__ Wh,
    const float* __restrict__ bz, const float* __restrict__ br, const float* __restrict__ bh)
{
    __shared__ float As[32 * 132];   // [k][m] transposed, padded stride 132
    __shared__ float Bs[32 * 64];    // [k][n]

    const int g = blockIdx.z;
    const float* W    = (g == 0) ? Wz : (g == 1) ? Wr : Wh;
    const float* bias = (g == 0) ? bz : (g == 1) ? br : bh;
    float* out = g_xp + (size_t)g * MH;

    const int mtile = blockIdx.x * 128;
    const int ntile = blockIdx.y * 64;
    const int tid = threadIdx.x;
    const int tm = tid >> 4;      // 0..15 -> 8 m-rows each
    const int tn = tid & 15;      // 0..15 -> 4 n-cols each

    float acc[8][4] = {};

    for (int kc = 0; kc < 128; kc += 32) {
        __syncthreads();
        // stage A chunk [128m x 32k] -> As[k][m]
        #pragma unroll
        for (int it = 0; it < 4; ++it) {
            int idx = tid + it * 256;          // float4 index, 0..1023
            int m = idx >> 3, c4 = idx & 7;
            float4 v = *(const float4*)&x[(size_t)(mtile + m) * 128 + kc + c4 * 4];
            As[(c4 * 4 + 0) * 132 + m] = v.x;
            As[(c4 * 4 + 1) * 132 + m] = v.y;
            As[(c4 * 4 + 2) * 132 + m] = v.z;
            As[(c4 * 4 + 3) * 132 + m] = v.w;
        }
        // stage B chunk [32k x 64n]
        #pragma unroll
        for (int it = 0; it < 2; ++it) {
            int idx = tid + it * 256;          // 0..511
            int kk = idx >> 4, n4 = idx & 15;
            float4 v = *(const float4*)&W[(size_t)(kc + kk) * 256 + ntile + n4 * 4];
            *(float4*)&Bs[kk * 64 + n4 * 4] = v;
        }
        __syncthreads();

        #pragma unroll
        for (int kk = 0; kk < 32; ++kk) {
            float4 a0 = *(const float4*)&As[kk * 132 + tm * 8];
            float4 a1 = *(const float4*)&As[kk * 132 + tm * 8 + 4];
            float4 bv = *(const float4*)&Bs[kk * 64 + tn * 4];
            float a[8] = {a0.x, a0.y, a0.z, a0.w, a1.x, a1.y, a1.z, a1.w};
            #pragma unroll
            for (int i = 0; i < 8; i++) {
                acc[i][0] += a[i] * bv.x;
                acc[i][1] += a[i] * bv.y;
                acc[i][2] += a[i] * bv.z;
                acc[i][3] += a[i] * bv.w;
            }
        }
    }

    float4 bb = *(const float4*)&bias[ntile + tn * 4];
    #pragma unroll
    for (int i = 0; i < 8; i++) {
        float4 o = make_float4(acc[i][0] + bb.x, acc[i][1] + bb.y,
                               acc[i][2] + bb.z, acc[i][3] + bb.w);
        *(float4*)&out[(size_t)(mtile + tm * 8 + i) * 256 + ntile + tn * 4] = o;
    }
}

// ================= barrier reset (graph replays must start clean) =================
__global__ void reset_kernel() {
    if (threadIdx.x < NBG * 2) ((unsigned*)g_ctr)[threadIdx.x] = 0;
}

// ================= group barrier among the 8 column-group CTAs =================
__device__ __forceinline__ void group_barrier(unsigned* ctr, unsigned tgt) {
    __threadfence();
    __syncthreads();
    if (threadIdx.x == 0) {
        atomicAdd(ctr, 1u);
        while (*(volatile unsigned*)ctr < tgt) __nanosleep(32);
        __threadfence();
    }
    __syncthreads();
}

// ================= persistent recurrent scan =================
// CTA = (batch group grp, column group cg). Each CTA holds U[:, cg*32 : cg*32+32]
// for all three gates in registers (k split across 8 warps, 32 k each).
__global__ __launch_bounds__(256, 1) void scan_kernel(
    const float* __restrict__ Uz, const float* __restrict__ Ur, const float* __restrict__ Uh,
    const float* __restrict__ hdecay, float* __restrict__ out)
{
    extern __shared__ float sm[];
    float* hdec_s = sm;              // [16][256]  (reused for rh in phase 3/4)
    float* red_z  = sm + 4096;       // [8][16][32] (reused for h partials)
    float* red_r  = sm + 8192;       // [8][16][32]

    const int tid = threadIdx.x;
    const int w = tid >> 5;          // warp -> k block [32w, 32w+32)
    const int l = tid & 31;          // lane -> local column
    const int grp = blockIdx.x >> 3;
    const int cg  = blockIdx.x & 7;
    const int jbase = cg * HC;
    const int j = jbase + l;         // global column
    const int b0g = grp * NB;        // global batch base

    // --- load weight slices into registers as packed f32x2 over k-pairs ---
    unsigned long long uz2[16], ur2[16], uh2[16];
    #pragma unroll
    for (int p = 0; p < 16; ++p) {
        int k = w * 32 + 2 * p;
        uz2[p] = pack2(Uz[(size_t)k * H_ + j], Uz[(size_t)(k + 1) * H_ + j]);
        ur2[p] = pack2(Ur[(size_t)k * H_ + j], Ur[(size_t)(k + 1) * H_ + j]);
        uh2[p] = pack2(Uh[(size_t)k * H_ + j], Uh[(size_t)(k + 1) * H_ + j]);
    }

    unsigned* ctr_rh = &g_ctr[grp][0];
    unsigned* ctr_h  = &g_ctr[grp][1];

    for (int t = 0; t < T_; ++t) {
        // This thread finalizes (b = w, j) and (b = w+8, j).
        const size_t m0 = (size_t)(b0g + w) * T_ + t;
        const size_t m1 = (size_t)(b0g + w + 8) * T_ + t;
        // prefetch projected inputs (HBM) early to hide latency behind GEMM
        float xz0 = g_xp[m0 * 256 + j],          xz1 = g_xp[m1 * 256 + j];
        float xr0 = g_xp[MH + m0 * 256 + j],     xr1 = g_xp[MH + m1 * 256 + j];
        float xh0 = g_xp[2 * MH + m0 * 256 + j], xh1 = g_xp[2 * MH + m1 * 256 + j];

        // ---- phase 0: hdec = dec_t * h_{t-1} into smem ----
        if (t == 0) {
            #pragma unroll
            for (int i = tid; i < NB * H_; i += 256) hdec_s[i] = 0.f;
        } else {
            #pragma unroll
            for (int it = 0; it < 4; ++it) {
                int idx = tid + it * 256;          // float4 index 0..1023
                int b = idx >> 6, k4 = idx & 63;
                float dec = hdecay[(size_t)(b0g + b) * T_ + t];
                float4 hv = *(const float4*)&g_h[grp][b][k4 * 4];
                float4 hd = make_float4(hv.x * dec, hv.y * dec, hv.z * dec, hv.w * dec);
                *(float4*)&hdec_s[b * 256 + k4 * 4] = hd;
            }
        }
        __syncthreads();

        // ---- phase 1: z,r partial dot products (weights in regs, f32x2) ----
        #pragma unroll 1
        for (int b = 0; b < NB; ++b) {
            unsigned long long az0 = 0, az1 = 0, ar0 = 0, ar1 = 0;
            const float* hrow = &hdec_s[b * 256 + w * 32];
            #pragma unroll
            for (int q = 0; q < 8; ++q) {
                ulonglong2 hv = *(const ulonglong2*)(hrow + q * 4);  // k-pairs (4q,4q+1),(4q+2,4q+3)
                fma2(az0, hv.x, uz2[2 * q]);
                fma2(az1, hv.y, uz2[2 * q + 1]);
                fma2(ar0, hv.x, ur2[2 * q]);
                fma2(ar1, hv.y, ur2[2 * q + 1]);
            }
            red_z[(w * 16 + b) * 32 + l] = fold2(az0) + fold2(az1);
            red_r[(w * 16 + b) * 32 + l] = fold2(ar0) + fold2(ar1);
        }
        __syncthreads();

        // ---- phase 2: reduce across warps, activations, write rh slice ----
        float zv0, zv1, hd0, hd1;
        {
            float sz0 = 0, sr0 = 0, sz1 = 0, sr1 = 0;
            #pragma unroll
            for (int ww = 0; ww < 8; ++ww) {
                sz0 += red_z[(ww * 16 + w) * 32 + l];
                sr0 += red_r[(ww * 16 + w) * 32 + l];
                sz1 += red_z[(ww * 16 + w + 8) * 32 + l];
                sr1 += red_r[(ww * 16 + w + 8) * 32 + l];
            }
            sz0 += xz0; sz1 += xz1; sr0 += xr0; sr1 += xr1;
            zv0 = sigmoid_(sz0); zv1 = sigmoid_(sz1);
            float r0 = sigmoid_(sr0), r1 = sigmoid_(sr1);
            hd0 = hdec_s[w * 256 + j];
            hd1 = hdec_s[(w + 8) * 256 + j];
            g_rh[grp][w][j]     = r0 * hd0;
            g_rh[grp][w + 8][j] = r1 * hd1;
        }
        group_barrier(ctr_rh, (unsigned)(t + 1) * NC);

        // ---- phase 3: pull full rh rows (overwrite hdec_s; hd kept in regs) ----
        #pragma unroll
        for (int it = 0; it < 4; ++it) {
            int idx = tid + it * 256;
            int b = idx >> 6, k4 = idx & 63;
            float4 v = *(const float4*)&g_rh[grp][b][k4 * 4];
            *(float4*)&hdec_s[b * 256 + k4 * 4] = v;
        }
        __syncthreads();

        // ---- phase 4: h_prop partial dot products ----
        #pragma unroll 1
        for (int b = 0; b < NB; ++b) {
            unsigned long long ah0 = 0, ah1 = 0;
            const float* hrow = &hdec_s[b * 256 + w * 32];
            #pragma unroll
            for (int q = 0; q < 8; ++q) {
                ulonglong2 hv = *(const ulonglong2*)(hrow + q * 4);
                fma2(ah0, hv.x, uh2[2 * q]);
                fma2(ah1, hv.y, uh2[2 * q + 1]);
            }
            red_z[(w * 16 + b) * 32 + l] = fold2(ah0) + fold2(ah1);
        }
        __syncthreads();

        // ---- phase 5: reduce, combine, write h + output ----
        {
            float sh0 = 0, sh1 = 0;
            #pragma unroll
            for (int ww = 0; ww < 8; ++ww) {
                sh0 += red_z[(ww * 16 + w) * 32 + l];
                sh1 += red_z[(ww * 16 + w + 8) * 32 + l];
            }
            sh0 += xh0; sh1 += xh1;
            float hp0 = tanh_(sh0), hp1 = tanh_(sh1);
            float h0 = (1.f - zv0) * hd0 + zv0 * hp0;
            float h1 = (1.f - zv1) * hd1 + zv1 * hp1;
            g_h[grp][w][j]     = h0;
            g_h[grp][w + 8][j] = h1;
            out[m0 * 256 + j] = h0;
            out[m1 * 256 + j] = h1;
        }
        group_barrier(ctr_h, (unsigned)(t + 1) * NC);
    }
}

// ================= launch =================
extern "C" void kernel_launch(void* const* d_in, const int* /*in_sizes*/, int /*n_in*/,
                              void* d_out, int /*out_size*/)
{
    const float* x      = (const float*)d_in[0];
    const float* hdecay = (const float*)d_in[1];
    const float* Wr = (const float*)d_in[2];
    const float* Wz = (const float*)d_in[3];
    const float* Wh = (const float*)d_in[4];
    const float* Ur = (const float*)d_in[5];
    const float* Uz = (const float*)d_in[6];
    const float* Uh = (const float*)d_in[7];
    const float* br = (const float*)d_in[8];
    const float* bz = (const float*)d_in[9];
    const float* bh = (const float*)d_in[10];
    float* out = (float*)d_out;

    // gate order in g_xp: 0 = z, 1 = r, 2 = h
    proj_kernel<<<dim3(MTOT / 128, H_ / 64, 3), 256>>>(x, Wz, Wr, Wh, bz, br, bh);
    reset_kernel<<<1, 32>>>();
    scan_kernel<<<NBG * NC, 256, 49152>>>(Uz, Ur, Uh, hdecay, out);
}